// round 2
// baseline (speedup 1.0000x reference)
#include <cuda_runtime.h>

#define NTOK 4096
#define NP1  4097
#define THREADS 512

// Constants from the reference:
#define CONTENT_PAD 1024.0f
#define CONTENT_EOS 1025.0f
#define CPOS_PAD 128.0f
#define CPOS_EOS 129.0f
#define MPOS_PAD 256.0f
#define MPOS_EOS 257.0f
#define FPOS_PAD 1024.0f
#define FPOS_EOS 1025.0f

__global__ __launch_bounds__(THREADS)
void permute_kernel(const int* __restrict__ indices,
                    const int* __restrict__ grains,
                    float* __restrict__ out,
                    long long M)   // elements per output tensor = rows * 4097
{
    const int b    = blockIdx.x;
    const int tid  = threadIdx.x;
    const int lane = tid & 31;
    const int warp = tid >> 5;

    // ---- load 8 tokens per thread (contiguous chunk -> stability) ----
    const int4* iv = (const int4*)(indices + (long long)b * NTOK);
    const int4* gv = (const int4*)(grains  + (long long)b * NTOK);
    int4 ia = iv[tid * 2], ib = iv[tid * 2 + 1];
    int4 ga = gv[tid * 2], gb = gv[tid * 2 + 1];
    int v[8] = {ia.x, ia.y, ia.z, ia.w, ib.x, ib.y, ib.z, ib.w};
    int g[8] = {ga.x, ga.y, ga.z, ga.w, gb.x, gb.y, gb.z, gb.w};

    // ---- packed local counts: c0 in [0:16), c1 in [16:32). c2 derived. ----
    unsigned packed = 0;
#pragma unroll
    for (int i = 0; i < 8; i++)
        packed += (g[i] == 0) ? 1u : ((g[i] == 1) ? 0x10000u : 0u);

    // ---- block exclusive scan (single packed u32: max count 4096 < 2^16) ----
    unsigned p = packed;
#pragma unroll
    for (int d = 1; d < 32; d <<= 1) {
        unsigned t = __shfl_up_sync(0xffffffffu, p, d);
        if (lane >= d) p += t;
    }
    __shared__ unsigned wsum[16];
    if (lane == 31) wsum[warp] = p;
    __syncthreads();
    if (warp == 0 && lane < 16) {
        unsigned x = wsum[lane];
#pragma unroll
        for (int d = 1; d < 16; d <<= 1) {
            unsigned t = __shfl_up_sync(0x0000ffffu, x, d);
            if (lane >= d) x += t;
        }
        wsum[lane] = x;
    }
    __syncthreads();
    const unsigned excl  = p - packed + (warp ? wsum[warp - 1] : 0u);
    const unsigned total = wsum[15];

    int p0 = (int)(excl & 0xFFFFu), p1 = (int)(excl >> 16);
    int p2 = tid * 8 - p0 - p1;
    const int c0 = (int)(total & 0xFFFFu), c1 = (int)(total >> 16);
    const int c2 = NTOK - c0 - c1;

    // ---- output tensor row bases (tuple order from reference) ----
    const long long rb = (long long)b * NP1;
    float* __restrict__ cc = out + 0 * M + rb;  // coarse_content
    float* __restrict__ mc = out + 1 * M + rb;  // medium_content
    float* __restrict__ fc = out + 2 * M + rb;  // fine_content
    float* __restrict__ cp = out + 3 * M + rb;  // coarse_position
    float* __restrict__ mp = out + 4 * M + rb;  // medium_position
    float* __restrict__ fp = out + 5 * M + rb;  // fine_position

    // ---- stable scatter of selected elements ----
    const int t0 = tid * 8;
#pragma unroll
    for (int i = 0; i < 8; i++) {
        const int gi = g[i];
        const float vi = (float)v[i];
        const float ti = (float)(t0 + i);
        if (gi == 0)      { cc[p0] = vi; cp[p0] = ti; p0++; }
        else if (gi == 1) { mc[p1] = vi; mp[p1] = ti; p1++; }
        else              { fc[p2] = vi; fp[p2] = ti; p2++; }
    }

    // ---- tails: EOS at cnt, PAD after (each slot written exactly once) ----
    for (int s = c0 + tid; s < NP1; s += THREADS) {
        cc[s] = (s == c0) ? CONTENT_EOS : CONTENT_PAD;
        cp[s] = (s == c0) ? CPOS_EOS    : CPOS_PAD;
    }
    for (int s = c1 + tid; s < NP1; s += THREADS) {
        mc[s] = (s == c1) ? CONTENT_EOS : CONTENT_PAD;
        mp[s] = (s == c1) ? MPOS_EOS    : MPOS_PAD;
    }
    for (int s = c2 + tid; s < NP1; s += THREADS) {
        fc[s] = (s == c2) ? CONTENT_EOS : CONTENT_PAD;
        fp[s] = (s == c2) ? FPOS_EOS    : FPOS_PAD;
    }

    // ---- segments: constant 0 / 1 / 2 ----
    float* __restrict__ s0 = out + 6 * M + rb;
    float* __restrict__ s1 = out + 7 * M + rb;
    float* __restrict__ s2 = out + 8 * M + rb;
    for (int s = tid; s < NP1; s += THREADS) {
        s0[s] = 0.0f; s1[s] = 1.0f; s2[s] = 2.0f;
    }
}

extern "C" void kernel_launch(void* const* d_in, const int* in_sizes, int n_in,
                              void* d_out, int out_size)
{
    const int* indices = (const int*)d_in[0];
    const int* grains  = (const int*)d_in[1];
    const int rows = in_sizes[0] / NTOK;            // 512
    const long long M = (long long)out_size / 9;    // elements per output tensor
    permute_kernel<<<rows, THREADS>>>(indices, grains, (float*)d_out, M);
}

// round 3
// speedup vs baseline: 1.6699x; 1.6699x over previous
#include <cuda_runtime.h>

#define NTOK 4096
#define NP1  4097
#define THREADS 512

__device__ __forceinline__ float comp(const unsigned short* __restrict__ buf,
                                      int s, int cnt, float eos, float pad)
{
    return s < cnt ? (float)buf[s] : (s == cnt ? eos : pad);
}

// Write one output row of NP1 floats: buf[0..cnt) then EOS then PAD.
// Aligned float4 body, scalar head/tail (row base alignment varies with b).
__device__ __forceinline__ void write_row(float* __restrict__ dst,
                                          const unsigned short* __restrict__ buf,
                                          int cnt, float eos, float pad, int tid)
{
    const int h = (int)((0u - ((unsigned)(size_t)dst >> 2)) & 3u);
    if (tid < h) dst[tid] = comp(buf, tid, cnt, eos, pad);
    const int nv = (NP1 - h) >> 2;
    float4* __restrict__ d4 = (float4*)(dst + h);
    for (int i = tid; i < nv; i += THREADS) {
        const int s = h + i * 4;
        float4 w;
        w.x = comp(buf, s,     cnt, eos, pad);
        w.y = comp(buf, s + 1, cnt, eos, pad);
        w.z = comp(buf, s + 2, cnt, eos, pad);
        w.w = comp(buf, s + 3, cnt, eos, pad);
        d4[i] = w;
    }
    const int base = h + nv * 4;
    if (tid < NP1 - base) dst[base + tid] = comp(buf, base + tid, cnt, eos, pad);
}

__device__ __forceinline__ void write_const_row(float* __restrict__ dst, float val, int tid)
{
    const int h = (int)((0u - ((unsigned)(size_t)dst >> 2)) & 3u);
    if (tid < h) dst[tid] = val;
    const int nv = (NP1 - h) >> 2;
    float4* __restrict__ d4 = (float4*)(dst + h);
    const float4 w = make_float4(val, val, val, val);
    for (int i = tid; i < nv; i += THREADS) d4[i] = w;
    const int base = h + nv * 4;
    if (tid < NP1 - base) dst[base + tid] = val;
}

__global__ __launch_bounds__(THREADS)
void permute_kernel(const int* __restrict__ indices,
                    const int* __restrict__ grains,
                    float* __restrict__ out,
                    long long M)
{
    __shared__ unsigned short cbuf[NTOK];   // compacted content (3 stream regions)
    __shared__ unsigned short pbuf[NTOK];   // compacted positions
    __shared__ unsigned wsum[16];

    const int b    = blockIdx.x;
    const int tid  = threadIdx.x;
    const int lane = tid & 31;
    const int warp = tid >> 5;

    // ---- load 8 tokens per thread (contiguous chunk -> stability) ----
    const int4* iv = (const int4*)(indices + (long long)b * NTOK);
    const int4* gv = (const int4*)(grains  + (long long)b * NTOK);
    int4 ia = iv[tid * 2], ib = iv[tid * 2 + 1];
    int4 ga = gv[tid * 2], gb = gv[tid * 2 + 1];
    int v[8] = {ia.x, ia.y, ia.z, ia.w, ib.x, ib.y, ib.z, ib.w};
    int g[8] = {ga.x, ga.y, ga.z, ga.w, gb.x, gb.y, gb.z, gb.w};

    // ---- packed local counts: c0 in [0:16), c1 in [16:32) ----
    unsigned packed = 0;
#pragma unroll
    for (int i = 0; i < 8; i++)
        packed += (g[i] == 0) ? 1u : ((g[i] == 1) ? 0x10000u : 0u);

    // ---- block inclusive scan of packed u32 (max 4096 per field) ----
    unsigned p = packed;
#pragma unroll
    for (int d = 1; d < 32; d <<= 1) {
        unsigned t = __shfl_up_sync(0xffffffffu, p, d);
        if (lane >= d) p += t;
    }
    if (lane == 31) wsum[warp] = p;
    __syncthreads();
    if (warp == 0 && lane < 16) {
        unsigned x = wsum[lane];
#pragma unroll
        for (int d = 1; d < 16; d <<= 1) {
            unsigned t = __shfl_up_sync(0x0000ffffu, x, d);
            if (lane >= d) x += t;
        }
        wsum[lane] = x;
    }
    __syncthreads();
    const unsigned excl  = p - packed + (warp ? wsum[warp - 1] : 0u);
    const unsigned total = wsum[15];

    const int e0 = (int)(excl & 0xFFFFu), e1 = (int)(excl >> 16);
    const int c0 = (int)(total & 0xFFFFu), c1 = (int)(total >> 16);
    const int c2 = NTOK - c0 - c1;

    // stream regions inside smem buffers: [0,c0) [c0,c0+c1) [c0+c1,4096)
    int q0 = e0;
    int q1 = c0 + e1;
    int q2 = c0 + c1 + (tid * 8 - e0 - e1);

    // ---- stable scatter into shared memory (cheap STS.U16) ----
    const int t0 = tid * 8;
#pragma unroll
    for (int i = 0; i < 8; i++) {
        const int gi = g[i];
        const unsigned short vi = (unsigned short)v[i];
        const unsigned short ti = (unsigned short)(t0 + i);
        if (gi == 0)      { cbuf[q0] = vi; pbuf[q0] = ti; q0++; }
        else if (gi == 1) { cbuf[q1] = vi; pbuf[q1] = ti; q1++; }
        else              { cbuf[q2] = vi; pbuf[q2] = ti; q2++; }
    }
    __syncthreads();

    // ---- coalesced vectorized output ----
    const long long rb = (long long)b * NP1;
    float* __restrict__ cc = out + 0 * M + rb;
    float* __restrict__ mc = out + 1 * M + rb;
    float* __restrict__ fc = out + 2 * M + rb;
    float* __restrict__ cp = out + 3 * M + rb;
    float* __restrict__ mp = out + 4 * M + rb;
    float* __restrict__ fp = out + 5 * M + rb;

    write_row(cc, cbuf,            c0, 1025.0f, 1024.0f, tid);
    write_row(mc, cbuf + c0,       c1, 1025.0f, 1024.0f, tid);
    write_row(fc, cbuf + c0 + c1,  c2, 1025.0f, 1024.0f, tid);
    write_row(cp, pbuf,            c0,  129.0f,  128.0f, tid);
    write_row(mp, pbuf + c0,       c1,  257.0f,  256.0f, tid);
    write_row(fp, pbuf + c0 + c1,  c2, 1025.0f, 1024.0f, tid);

    write_const_row(out + 6 * M + rb, 0.0f, tid);
    write_const_row(out + 7 * M + rb, 1.0f, tid);
    write_const_row(out + 8 * M + rb, 2.0f, tid);
}

extern "C" void kernel_launch(void* const* d_in, const int* in_sizes, int n_in,
                              void* d_out, int out_size)
{
    const int* indices = (const int*)d_in[0];
    const int* grains  = (const int*)d_in[1];
    const int rows = in_sizes[0] / NTOK;            // 512
    const long long M = (long long)out_size / 9;    // elements per output tensor
    permute_kernel<<<rows, THREADS>>>(indices, grains, (float*)d_out, M);
}

// round 4
// speedup vs baseline: 1.7686x; 1.0591x over previous
#include <cuda_runtime.h>

#define NTOK 4096
#define NP1  4097
#define THREADS 512

__device__ __forceinline__ float comp(const float* __restrict__ buf,
                                      int s, int cnt, float eos, float pad)
{
    return s < cnt ? buf[s] : (s == cnt ? eos : pad);
}

// Write one output row of NP1 floats: buf[0..cnt) then EOS then PAD.
// Chunk-classified float4 body; scalar head/tail for row-base misalignment.
__device__ __forceinline__ void write_row(float* __restrict__ dst,
                                          const float* __restrict__ buf,
                                          int cnt, float eos, float pad, int tid)
{
    const int h = (int)((0u - ((unsigned)(size_t)dst >> 2)) & 3u);
    if (tid < h) dst[tid] = comp(buf, tid, cnt, eos, pad);
    const int nv = (NP1 - h) >> 2;
    float4* __restrict__ d4 = (float4*)(dst + h);
    const float4 pad4 = make_float4(pad, pad, pad, pad);
#pragma unroll 2
    for (int i = tid; i < nv; i += THREADS) {
        const int s = h + i * 4;
        float4 w;
        if (s + 3 < cnt) {                     // pure content chunk
            w.x = buf[s]; w.y = buf[s + 1]; w.z = buf[s + 2]; w.w = buf[s + 3];
        } else if (s > cnt) {                  // pure PAD chunk (no LDS)
            w = pad4;
        } else {                               // boundary chunk (per-element)
            w.x = comp(buf, s,     cnt, eos, pad);
            w.y = comp(buf, s + 1, cnt, eos, pad);
            w.z = comp(buf, s + 2, cnt, eos, pad);
            w.w = comp(buf, s + 3, cnt, eos, pad);
        }
        d4[i] = w;
    }
    const int base = h + nv * 4;
    if (tid < NP1 - base) dst[base + tid] = comp(buf, base + tid, cnt, eos, pad);
}

__device__ __forceinline__ void write_const_row(float* __restrict__ dst, float val, int tid)
{
    const int h = (int)((0u - ((unsigned)(size_t)dst >> 2)) & 3u);
    if (tid < h) dst[tid] = val;
    const int nv = (NP1 - h) >> 2;
    float4* __restrict__ d4 = (float4*)(dst + h);
    const float4 w = make_float4(val, val, val, val);
#pragma unroll 2
    for (int i = tid; i < nv; i += THREADS) d4[i] = w;
    const int base = h + nv * 4;
    if (tid < NP1 - base) dst[base + tid] = val;
}

__global__ __launch_bounds__(THREADS)
void permute_kernel(const int* __restrict__ indices,
                    const int* __restrict__ grains,
                    float* __restrict__ out,
                    long long M)
{
    __shared__ float cbuf[NTOK];    // compacted content (3 stream regions), as float
    __shared__ float pbuf[NTOK];    // compacted positions, as float
    __shared__ unsigned wsum[16];

    const int b    = blockIdx.x;
    const int tid  = threadIdx.x;
    const int lane = tid & 31;
    const int warp = tid >> 5;

    // ---- load 8 tokens per thread (contiguous chunk -> stability) ----
    const int4* iv = (const int4*)(indices + (long long)b * NTOK);
    const int4* gv = (const int4*)(grains  + (long long)b * NTOK);
    int4 ia = iv[tid * 2], ib = iv[tid * 2 + 1];
    int4 ga = gv[tid * 2], gb = gv[tid * 2 + 1];
    int v[8] = {ia.x, ia.y, ia.z, ia.w, ib.x, ib.y, ib.z, ib.w};
    int g[8] = {ga.x, ga.y, ga.z, ga.w, gb.x, gb.y, gb.z, gb.w};

    // ---- packed local counts: c0 in [0:16), c1 in [16:32) ----
    unsigned packed = 0;
#pragma unroll
    for (int i = 0; i < 8; i++)
        packed += (g[i] == 0) ? 1u : ((g[i] == 1) ? 0x10000u : 0u);

    // ---- block inclusive scan of packed u32 (max 4096 per field) ----
    unsigned p = packed;
#pragma unroll
    for (int d = 1; d < 32; d <<= 1) {
        unsigned t = __shfl_up_sync(0xffffffffu, p, d);
        if (lane >= d) p += t;
    }
    if (lane == 31) wsum[warp] = p;
    __syncthreads();
    if (warp == 0 && lane < 16) {
        unsigned x = wsum[lane];
#pragma unroll
        for (int d = 1; d < 16; d <<= 1) {
            unsigned t = __shfl_up_sync(0x0000ffffu, x, d);
            if (lane >= d) x += t;
        }
        wsum[lane] = x;
    }
    __syncthreads();
    const unsigned excl  = p - packed + (warp ? wsum[warp - 1] : 0u);
    const unsigned total = wsum[15];

    const int e0 = (int)(excl & 0xFFFFu), e1 = (int)(excl >> 16);
    const int c0 = (int)(total & 0xFFFFu), c1 = (int)(total >> 16);
    const int c2 = NTOK - c0 - c1;

    // stream regions inside smem buffers: [0,c0) [c0,c0+c1) [c0+c1,4096)
    int q0 = e0;
    int q1 = c0 + e1;
    int q2 = c0 + c1 + (tid * 8 - e0 - e1);

    // ---- stable scatter into shared memory (floats, converted once) ----
    const int t0 = tid * 8;
#pragma unroll
    for (int i = 0; i < 8; i++) {
        const int gi = g[i];
        const float vi = (float)v[i];
        const float ti = (float)(t0 + i);
        if (gi == 0)      { cbuf[q0] = vi; pbuf[q0] = ti; q0++; }
        else if (gi == 1) { cbuf[q1] = vi; pbuf[q1] = ti; q1++; }
        else              { cbuf[q2] = vi; pbuf[q2] = ti; q2++; }
    }
    __syncthreads();

    // ---- coalesced vectorized output ----
    const long long rb = (long long)b * NP1;
    float* __restrict__ cc = out + 0 * M + rb;
    float* __restrict__ mc = out + 1 * M + rb;
    float* __restrict__ fc = out + 2 * M + rb;
    float* __restrict__ cp = out + 3 * M + rb;
    float* __restrict__ mp = out + 4 * M + rb;
    float* __restrict__ fp = out + 5 * M + rb;

    write_row(cc, cbuf,            c0, 1025.0f, 1024.0f, tid);
    write_row(mc, cbuf + c0,       c1, 1025.0f, 1024.0f, tid);
    write_row(fc, cbuf + c0 + c1,  c2, 1025.0f, 1024.0f, tid);
    write_row(cp, pbuf,            c0,  129.0f,  128.0f, tid);
    write_row(mp, pbuf + c0,       c1,  257.0f,  256.0f, tid);
    write_row(fp, pbuf + c0 + c1,  c2, 1025.0f, 1024.0f, tid);

    write_const_row(out + 6 * M + rb, 0.0f, tid);
    write_const_row(out + 7 * M + rb, 1.0f, tid);
    write_const_row(out + 8 * M + rb, 2.0f, tid);
}

extern "C" void kernel_launch(void* const* d_in, const int* in_sizes, int n_in,
                              void* d_out, int out_size)
{
    const int* indices = (const int*)d_in[0];
    const int* grains  = (const int*)d_in[1];
    const int rows = in_sizes[0] / NTOK;            // 512
    const long long M = (long long)out_size / 9;    // elements per output tensor
    permute_kernel<<<rows, THREADS>>>(indices, grains, (float*)d_out, M);
}